// round 17
// baseline (speedup 1.0000x reference)
#include <cuda_runtime.h>
#include <cuda_bf16.h>
#include <cstdint>
#include <cstddef>

#define N_ROWS   262144
#define DDIM     64
#define QSTAGES  8
#define KCODES   1024
#define TMK      128
#define NCH      128            // cols per chunk
#define NCHUNKS  (KCODES / NCH)
#define NTHREADS 256
#define RS       68             // s_r row stride (fp32) — multiple of 4!
#define SB       72             // B smem row stride (bf16) -> 144B rows

// eps = EPSC * ||r|| * max||c|| + EPSA.
// Hard bound: |d~ - d| <= 2*(2^-8*1.005)*||r||*||c|| each candidate
// => separation needs 2x = 1.575e-2; EPSC=1.7e-2 gives ~8% margin.
#define EPSC 1.7e-2f
#define EPSA 1e-5f

// ---- smem layout (float units) ----
// TOP/IDX/FQ alias B buffer 1 (lifetimes disjoint: written after the chunk
// loop's last sync, consumed before next stage's c=0 staging of buf 1).
#define OFF_R        0                        // 128*68 = 8704 fp32
#define BBUF_FLOATS  4608                     // one buf: hi only, 18432 B
#define OFF_B        8704                     // 2 bufs x 4608 fp32
#define OFF_TOP      (OFF_B + BBUF_FLOATS)    // 13312 (aliases buf 1): 1280
#define OFF_IDX      (OFF_TOP + 1280)         // 14592: 128 ints
#define OFF_FQ       (OFF_IDX + 128)          // 14720: cnt, mx, queue[128]
#define OFF_HN       (OFF_B + 2 * BBUF_FLOATS) // 17920
#define SMEM_FLOATS  (OFF_HN + KCODES)        // 18944
#define SMEM_BYTES   (SMEM_FLOATS * 4)        // 75,776 B (x2 CTAs = 151,552)

#define BBUF_BYTES 18432

__device__ float g_hn[QSTAGES * KCODES];
__device__ float g_mx[QSTAGES];
__device__ __nv_bfloat16 g_cbh[QSTAGES * KCODES * DDIM];
__device__ float g_qscratch[(size_t)N_ROWS * DDIM];

// ================= asm helpers (baseline PTX only) =================
__device__ __forceinline__ uint32_t smem_u32_of(const void* p) {
    uint32_t a;
    asm("{ .reg .u64 t; cvta.to.shared.u64 t, %1; cvt.u32.u64 %0, t; }"
        : "=r"(a) : "l"(p));
    return a;
}
__device__ __forceinline__ void ldsm_x4(uint32_t& r0, uint32_t& r1,
                                        uint32_t& r2, uint32_t& r3,
                                        uint32_t addr) {
    asm volatile("ldmatrix.sync.aligned.m8n8.x4.shared.b16 {%0,%1,%2,%3}, [%4];"
                 : "=r"(r0), "=r"(r1), "=r"(r2), "=r"(r3) : "r"(addr));
}
__device__ __forceinline__ void mma_bf16(float* d, const uint32_t* a,
                                         uint32_t b0, uint32_t b1) {
    asm volatile(
        "mma.sync.aligned.m16n8k16.row.col.f32.bf16.bf16.f32 "
        "{%0,%1,%2,%3}, {%4,%5,%6,%7}, {%8,%9}, {%0,%1,%2,%3};"
        : "+f"(d[0]), "+f"(d[1]), "+f"(d[2]), "+f"(d[3])
        : "r"(a[0]), "r"(a[1]), "r"(a[2]), "r"(a[3]), "r"(b0), "r"(b1));
}
__device__ __forceinline__ void cp16(uint32_t dst, const void* src) {
    asm volatile("cp.async.cg.shared.global [%0], [%1], 16;"
                 :: "r"(dst), "l"(src) : "memory");
}
#define CP_COMMIT() asm volatile("cp.async.commit_group;" ::: "memory")
#define CP_WAIT0()  asm volatile("cp.async.wait_group 0;" ::: "memory")
#define CP_WAIT1()  asm volatile("cp.async.wait_group 1;" ::: "memory")

__device__ __forceinline__ uint32_t pack_split(float f0, float f1,
                                               uint32_t& lo) {
    __nv_bfloat16 h0 = __float2bfloat16_rn(f0);
    __nv_bfloat16 h1 = __float2bfloat16_rn(f1);
    __nv_bfloat16 g0 = __float2bfloat16_rn(f0 - __bfloat162float(h0));
    __nv_bfloat16 g1 = __float2bfloat16_rn(f1 - __bfloat162float(h1));
    lo = (uint32_t)__bfloat16_as_ushort(g0) |
         ((uint32_t)__bfloat16_as_ushort(g1) << 16);
    return (uint32_t)__bfloat16_as_ushort(h0) |
           ((uint32_t)__bfloat16_as_ushort(h1) << 16);
}

// ================= prep kernels =================
__global__ void hn_kernel(const float* __restrict__ cb) {
    int warp = (blockIdx.x * blockDim.x + threadIdx.x) >> 5;
    int lane = threadIdx.x & 31;
    if (warp < QSTAGES * KCODES) {
        const float* row = cb + (size_t)warp * DDIM;
        float c0 = row[lane];
        float c1 = row[lane + 32];
        float acc = __fmaf_rn(c0, c0, 0.0f);
        acc = __fmaf_rn(c1, c1, acc);
#pragma unroll
        for (int off = 16; off > 0; off >>= 1)
            acc = acc + __shfl_down_sync(0xffffffffu, acc, off);
        if (lane == 0) g_hn[warp] = acc;
    }
}
__global__ void mx_kernel() {
    __shared__ float red[256];
    int q = blockIdx.x, tid = threadIdx.x;
    float m = 0.f;
    for (int i = tid; i < KCODES; i += 256) m = fmaxf(m, g_hn[q * KCODES + i]);
    red[tid] = m; __syncthreads();
    for (int s = 128; s > 0; s >>= 1) {
        if (tid < s) red[tid] = fmaxf(red[tid], red[tid + s]);
        __syncthreads();
    }
    if (tid == 0) g_mx[q] = red[0];
}
__global__ void split_kernel(const float* __restrict__ cb) {
    int gid = blockIdx.x * blockDim.x + threadIdx.x;
    if (gid >= QSTAGES * KCODES) return;
    const float* src = cb + (size_t)gid * DDIM;
    __nv_bfloat16* bh = g_cbh + (size_t)gid * DDIM;
#pragma unroll
    for (int d = 0; d < DDIM; d++)
        bh[d] = __float2bfloat16_rn(src[d]);
}

// top-3 update (values; indices for top-2 only). Strict < keeps first-seen.
__device__ __forceinline__ void upd3(float& v1, int& i1, float& v2, int& i2,
                                     float& v3, float dv, int col) {
    if (dv < v1)      { v3 = v2; v2 = v1; i2 = i1; v1 = dv; i1 = col; }
    else if (dv < v2) { v3 = v2; v2 = dv; i2 = col; }
    else if (dv < v3) { v3 = dv; }
}
// merge two top-3 triples (value ordering only; index ties immaterial —
// both top-2 indices get exact reranking).
__device__ __forceinline__ void merge3(float& v1, int& i1, float& v2, int& i2,
                                       float& v3, float ov1, int oi1,
                                       float ov2, int oi2, float ov3) {
    if (ov1 < v1) {
        float nv2; int ni2; float nv3;
        if (v1 < ov2) { nv2 = v1; ni2 = i1; nv3 = fminf(v2, ov2); }
        else          { nv2 = ov2; ni2 = oi2; nv3 = fminf(v1, ov3); }
        v3 = nv3; v2 = nv2; i2 = ni2; v1 = ov1; i1 = oi1;
    } else {
        if (ov1 < v2) { v3 = fminf(v2, ov2); v2 = ov1; i2 = oi1; }
        else          { v3 = fminf(v3, ov1); }
    }
}

// ================= main kernel =================
__global__ void __launch_bounds__(NTHREADS, 2)
rvq_mma_kernel(const float* __restrict__ x, const float* __restrict__ cb,
               float* __restrict__ qbuf, float* __restrict__ enc_f,
               int* __restrict__ enc_i) {
    extern __shared__ float smem[];
    float* s_r   = smem + OFF_R;
    float* s_hn  = smem + OFF_HN;
    float* s_top = smem + OFF_TOP;
    int*   s_idx = (int*)(smem + OFF_IDX);
    int*   s_fq  = (int*)(smem + OFF_FQ);

    const int tid = threadIdx.x;
    const int wid = tid >> 5;
    const int lane = tid & 31;
    const int g = lane >> 2;          // 0..7
    const int qd = lane & 3;          // 0..3
    const int rhalf = wid & 3;        // row quarter (32 rows)
    const int chalf = wid >> 2;       // col half (64 cols)
    const int row_base = blockIdx.x * TMK;
    const uint32_t sm_b = smem_u32_of(smem) + OFF_B * 4;
    const uint32_t lm_off = ((uint32_t)(lane & 7) * SB + (uint32_t)(lane >> 3) * 8) * 2
                          + (uint32_t)chalf * 64 * SB * 2;

    // ---- init residual = x ----
    {
        int row = tid >> 1, dh = (tid & 1) << 5;
        const float4* xp = (const float4*)(x + (size_t)(row_base + row) * DDIM + dh);
#pragma unroll
        for (int j = 0; j < 8; j++)
            *(float4*)(s_r + row * RS + dh + (j << 2)) = xp[j];
    }

    for (int qs = 0; qs < QSTAGES; qs++) {
        const float* cbq = cb + (size_t)qs * (KCODES * DDIM);
        const __nv_bfloat16* cbh = g_cbh + (size_t)qs * (KCODES * DDIM);

#pragma unroll
        for (int i = 0; i < KCODES / NTHREADS; i++)
            s_hn[tid + i * NTHREADS] = g_hn[qs * KCODES + tid + i * NTHREADS];
        __syncthreads();

        // ---- A fragments (32 rows per warp, 2 rowfrags), bf16 hi+lo ----
        uint32_t ah[2][4][4], al[2][4][4];
        {
            int rlo = rhalf * 32 + g;
#pragma unroll
            for (int rf = 0; rf < 2; rf++)
#pragma unroll
                for (int f = 0; f < 4; f++)
#pragma unroll
                    for (int p = 0; p < 4; p++) {
                        int row = rlo + rf * 16 + ((p & 1) << 3);
                        int kk = f * 16 + ((p >> 1) << 3) + (qd << 1);
                        float2 v = *(const float2*)(s_r + row * RS + kk);
                        ah[rf][f][p] = pack_split(v.x, v.y, al[rf][f][p]);
                    }
        }

        // ---- stage chunk 0 (cp.async, hi only) into buf 0 ----
        {
#pragma unroll
            for (int t = 0; t < 4; t++) {
                int idx = t * 256 + tid;        // 1024 16B units
                int n = idx >> 3, j = idx & 7;
                uint32_t doff = (uint32_t)n * 144 + (uint32_t)j * 16;
                cp16(sm_b + doff, (const char*)(cbh + (size_t)n * DDIM) + j * 16);
            }
            CP_COMMIT();
        }

        // top-3 state: 4 row slots (rf*2 + {row g, row g+8})
        float v1[4], v2[4], v3[4];
        int i1[4], i2[4];
#pragma unroll
        for (int s = 0; s < 4; s++) {
            v1[s] = 3.0e38f; v2[s] = 3.0e38f; v3[s] = 3.0e38f;
            i1[s] = 0x7fffffff; i2[s] = 0x7fffffff;
        }

        for (int c = 0; c < NCHUNKS; c++) {
            if (c < NCHUNKS - 1) {
                uint32_t dsth = sm_b + (uint32_t)((c + 1) & 1) * BBUF_BYTES;
                const __nv_bfloat16* sh = cbh + (size_t)(c + 1) * NCH * DDIM;
#pragma unroll
                for (int t = 0; t < 4; t++) {
                    int idx = t * 256 + tid;
                    int n = idx >> 3, j = idx & 7;
                    uint32_t doff = (uint32_t)n * 144 + (uint32_t)j * 16;
                    cp16(dsth + doff, (const char*)(sh + (size_t)n * DDIM) + j * 16);
                }
                CP_COMMIT();
                CP_WAIT1();
            } else {
                CP_WAIT0();
            }
            __syncthreads();

            const uint32_t bh_base = sm_b + (uint32_t)(c & 1) * BBUF_BYTES + lm_off;

#pragma unroll 2
            for (int nt = 0; nt < 8; nt++) {
                uint32_t ro = (uint32_t)nt * (8 * SB * 2);
                uint32_t bh[8];
                ldsm_x4(bh[0], bh[1], bh[2], bh[3], bh_base + ro);
                ldsm_x4(bh[4], bh[5], bh[6], bh[7], bh_base + ro + 64);

                int cbase = c * NCH + chalf * 64 + nt * 8 + (qd << 1);
                float2 hv = *(const float2*)(s_hn + cbase);

#pragma unroll
                for (int rf = 0; rf < 2; rf++) {
                    // 2-pass fused accumulator: (ah + al) x bh
                    float d[4] = {0.f, 0.f, 0.f, 0.f};
#pragma unroll
                    for (int f = 0; f < 4; f++)
                        mma_bf16(d, ah[rf][f], bh[2 * f], bh[2 * f + 1]);
#pragma unroll
                    for (int f = 0; f < 4; f++)
                        mma_bf16(d, al[rf][f], bh[2 * f], bh[2 * f + 1]);

                    float dv0 = __fmaf_rn(-2.0f, d[0], hv.x);
                    float dv1 = __fmaf_rn(-2.0f, d[1], hv.y);
                    float dv2 = __fmaf_rn(-2.0f, d[2], hv.x);
                    float dv3 = __fmaf_rn(-2.0f, d[3], hv.y);
                    int s0 = rf * 2, s1 = rf * 2 + 1;
                    upd3(v1[s0], i1[s0], v2[s0], i2[s0], v3[s0], dv0, cbase);
                    upd3(v1[s0], i1[s0], v2[s0], i2[s0], v3[s0], dv1, cbase + 1);
                    upd3(v1[s1], i1[s1], v2[s1], i2[s1], v3[s1], dv2, cbase);
                    upd3(v1[s1], i1[s1], v2[s1], i2[s1], v3[s1], dv3, cbase + 1);
                }
            }
            __syncthreads();
        }
        // From here, buf 1 region reused for s_top / s_idx / s_fq.

        // ---- quad merge (lanes with same g share rows) ----
#pragma unroll
        for (int s = 0; s < 4; s++) {
#pragma unroll
            for (int off = 1; off <= 2; off <<= 1) {
                float ov1 = __shfl_xor_sync(0xffffffffu, v1[s], off);
                int oi1 = __shfl_xor_sync(0xffffffffu, i1[s], off);
                float ov2 = __shfl_xor_sync(0xffffffffu, v2[s], off);
                int oi2 = __shfl_xor_sync(0xffffffffu, i2[s], off);
                float ov3 = __shfl_xor_sync(0xffffffffu, v3[s], off);
                merge3(v1[s], i1[s], v2[s], i2[s], v3[s], ov1, oi1, ov2, oi2, ov3);
            }
        }
        if (qd == 0) {
            int rlo = rhalf * 32 + g;
#pragma unroll
            for (int s = 0; s < 4; s++) {
                int row = rlo + ((s & 1) << 3) + ((s >> 1) << 4);
                float* t = s_top + row * 10 + chalf * 5;
                t[0] = v1[s];
                t[1] = __int_as_float(i1[s]);
                t[2] = v2[s];
                t[3] = __int_as_float(i2[s]);
                t[4] = v3[s];
            }
        }
        if (tid == 0) { s_fq[0] = 0; ((float*)s_fq)[1] = g_mx[qs]; }
        __syncthreads();

        // ---- merge col halves, eps gate, exact pair rerank ----
        if (tid < TMK) {
            const float* t = s_top + tid * 10;
            float w1 = t[0]; int wi1 = __float_as_int(t[1]);
            float w2 = t[2]; int wi2 = __float_as_int(t[3]);
            float w3 = t[4];
            merge3(w1, wi1, w2, wi2, w3,
                   t[5], __float_as_int(t[6]), t[7], __float_as_int(t[8]), t[9]);

            const float* rr = s_r + tid * RS;
            float pn = 0.f;
#pragma unroll
            for (int u = 0; u < 16; u++) {
                float4 v = *(const float4*)(rr + (u << 2));
                pn = __fmaf_rn(v.x, v.x, pn); pn = __fmaf_rn(v.y, v.y, pn);
                pn = __fmaf_rn(v.z, v.z, pn); pn = __fmaf_rn(v.w, v.w, pn);
            }
            float mx = ((float*)s_fq)[1];
            float eps = EPSC * __fsqrt_rn(pn * mx) + EPSA;
            if (w3 - w1 > eps) {
                // true fp32 argmin is provably in {wi1, wi2}:
                // exact ref-order rerank of the pair.
                const float4* ca = (const float4*)(cbq + (size_t)wi1 * DDIM);
                const float4* cbp = (const float4*)(cbq + (size_t)wi2 * DDIM);
                float sa = 0.f, sb = 0.f;
#pragma unroll
                for (int u = 0; u < 16; u++) {
                    float4 va = ca[u], vb = cbp[u];
                    const float* rv = rr + (u << 2);
                    sa = __fmaf_rn(rv[0], va.x, sa);
                    sa = __fmaf_rn(rv[1], va.y, sa);
                    sa = __fmaf_rn(rv[2], va.z, sa);
                    sa = __fmaf_rn(rv[3], va.w, sa);
                    sb = __fmaf_rn(rv[0], vb.x, sb);
                    sb = __fmaf_rn(rv[1], vb.y, sb);
                    sb = __fmaf_rn(rv[2], vb.z, sb);
                    sb = __fmaf_rn(rv[3], vb.w, sb);
                }
                float da = __fmaf_rn(-2.0f, sa, s_hn[wi1]);
                float db = __fmaf_rn(-2.0f, sb, s_hn[wi2]);
                int sel;
                if (da < db || (da == db && wi1 < wi2)) sel = wi1;
                else sel = wi2;
                s_idx[tid] = sel;
            } else {
                int p = atomicAdd(&s_fq[0], 1);
                s_fq[2 + p] = tid;
            }
        }
        __syncthreads();

        // ---- slow path: exact fp32 full-row scan (bit-exact ref order) ----
        {
            int nflag = s_fq[0];
            for (int i = wid; i < nflag; i += 8) {
                int row = s_fq[2 + i];
                float bd = 3.0e38f; int bi_ = 0x7fffffff;
                const float* rrow = s_r + row * RS;
#pragma unroll 1
                for (int j = 0; j < 32; j++) {
                    int col = lane + (j << 5);
                    const float4* cp = (const float4*)(cbq + (size_t)col * DDIM);
                    float acc = 0.f;
#pragma unroll
                    for (int u = 0; u < 16; u++) {
                        float4 cv = cp[u];
                        const float* rv = rrow + (u << 2);
                        acc = __fmaf_rn(rv[0], cv.x, acc);
                        acc = __fmaf_rn(rv[1], cv.y, acc);
                        acc = __fmaf_rn(rv[2], cv.z, acc);
                        acc = __fmaf_rn(rv[3], cv.w, acc);
                    }
                    float dv = __fmaf_rn(-2.0f, acc, s_hn[col]);
                    if (dv < bd) { bd = dv; bi_ = col; }
                }
#pragma unroll
                for (int off = 16; off > 0; off >>= 1) {
                    float ov = __shfl_xor_sync(0xffffffffu, bd, off);
                    int oi = __shfl_xor_sync(0xffffffffu, bi_, off);
                    if (ov < bd || (ov == bd && oi < bi_)) { bd = ov; bi_ = oi; }
                }
                if (lane == 0) s_idx[row] = bi_;
            }
        }
        __syncthreads();

        // ---- enc write + q/r update (bit-exact, validated) ----
        if (tid < TMK) {
            int id = s_idx[tid];
            size_t e = (size_t)(row_base + tid) * QSTAGES + qs;
            if (enc_f) enc_f[e] = (float)id;
            if (enc_i) enc_i[e] = id;
        }
        {
            int row = tid >> 1, dh = (tid & 1) << 5;
            int id = s_idx[row];
            const float4* cp = (const float4*)(cbq + (size_t)id * DDIM + dh);
            const float4* xp = (const float4*)(x + (size_t)(row_base + row) * DDIM + dh);
            float* qrow = qbuf + (size_t)(row_base + row) * DDIM + dh;
#pragma unroll
            for (int j = 0; j < 8; j++) {
                float4 cv = cp[j];
                float4 xv = xp[j];
                float4 qv;
                if (qs == 0) { qv.x = qv.y = qv.z = qv.w = 0.f; }
                else qv = *(const float4*)(qrow + (j << 2));
                float q0 = qv.x + cv.x, q1 = qv.y + cv.y;
                float q2 = qv.z + cv.z, q3 = qv.w + cv.w;
                float4 qo; qo.x = q0; qo.y = q1; qo.z = q2; qo.w = q3;
                *(float4*)(qrow + (j << 2)) = qo;
                float4 ro;
                ro.x = xv.x - q0; ro.y = xv.y - q1;
                ro.z = xv.z - q2; ro.w = xv.w - q3;
                *(float4*)(s_r + row * RS + dh + (j << 2)) = ro;
            }
        }
        __syncthreads();
    }
}

// ---------------- launch ----------------
extern "C" void kernel_launch(void* const* d_in, const int* in_sizes, int n_in,
                              void* d_out, int out_size) {
    const float* x = (const float*)d_in[0];
    const float* cb = (const float*)d_in[1];
    if (n_in >= 2 && in_sizes[0] == QSTAGES * KCODES * DDIM &&
        in_sizes[1] == N_ROWS * DDIM) {
        x = (const float*)d_in[1];
        cb = (const float*)d_in[0];
    }

    cudaFuncSetAttribute(rvq_mma_kernel,
                         cudaFuncAttributeMaxDynamicSharedMemorySize, SMEM_BYTES);

    hn_kernel<<<(QSTAGES * KCODES * 32 + 255) / 256, 256>>>(cb);
    mx_kernel<<<QSTAGES, 256>>>();
    split_kernel<<<(QSTAGES * KCODES + 255) / 256, 256>>>(cb);

    const long long enc_n = (long long)N_ROWS * QSTAGES;
    const long long qz_n = (long long)N_ROWS * DDIM;

    float* qz = nullptr;
    float* enc_f = nullptr;
    int* enc_i = nullptr;
    if ((long long)out_size == enc_n + qz_n) {
        enc_f = (float*)d_out;
        qz = (float*)d_out + enc_n;
    } else if ((long long)out_size == qz_n) {
        qz = (float*)d_out;
    } else if ((long long)out_size == enc_n) {
        enc_i = (int*)d_out;
    } else {
        enc_f = (float*)d_out;
        if ((long long)out_size >= enc_n + qz_n) qz = (float*)d_out + enc_n;
    }

    float* qbuf = qz;
    if (!qbuf) cudaGetSymbolAddress((void**)&qbuf, g_qscratch);

    rvq_mma_kernel<<<N_ROWS / TMK, NTHREADS, SMEM_BYTES>>>(x, cb, qbuf,
                                                           enc_f, enc_i);
}